// round 14
// baseline (speedup 1.0000x reference)
#include <cuda_runtime.h>

#define N_NODES 100000
#define N_EDGES 1600000
#define N_PE    200000
#define F1 128
#define F2 8
#define SCAN_B 1024
#define N_SCAN_BLK ((N_NODES + SCAN_B - 1) / SCAN_B)   // 98

// Scratch (static device globals — no allocation allowed)
__device__ __align__(16) float g_hs1[N_NODES * F1];   // dinv-scaled x@W1
__device__ __align__(16) float g_hs2[N_NODES * F2];   // dinv-scaled h@W2
__device__ __align__(16) float g_z[N_NODES * F2];     // layer-2 output
__device__ __align__(16) float g_dinv[N_NODES];
__device__ __align__(16) int   g_deg[N_NODES];
__device__ __align__(16) int   g_row_start[N_NODES];  // exclusive prefix of deg
__device__ __align__(16) int   g_cursor[N_NODES];     // fill cursors
__device__ __align__(16) int   g_csr_src[N_EDGES];    // src grouped by dst
__device__ __align__(16) int   g_bsum[N_SCAN_BLK];
__device__ __align__(16) int   g_boff[N_SCAN_BLK];

// ---------------------------------------------------------------------------
__global__ __launch_bounds__(256) void zero_deg_kernel() {
    int i = blockIdx.x * blockDim.x + threadIdx.x;
    if (i < N_NODES) g_deg[i] = 0;
}

__global__ __launch_bounds__(256) void deg_kernel(const int* __restrict__ dst) {
    int e = blockIdx.x * blockDim.x + threadIdx.x;
    if (e < N_EDGES) atomicAdd(&g_deg[dst[e]], 1);
}

__global__ __launch_bounds__(256) void dinv_kernel() {
    int i = blockIdx.x * blockDim.x + threadIdx.x;
    if (i < N_NODES) g_dinv[i] = rsqrtf((float)g_deg[i] + 1.0f);
}

// --- prefix sum of g_deg -> g_row_start (exclusive), 3 phases ---------------
__global__ __launch_bounds__(SCAN_B) void scan1_kernel() {
    __shared__ int s[SCAN_B];
    int tid = threadIdx.x;
    int i = blockIdx.x * SCAN_B + tid;
    int v = (i < N_NODES) ? g_deg[i] : 0;
    s[tid] = v;
    __syncthreads();
#pragma unroll
    for (int off = 1; off < SCAN_B; off <<= 1) {
        int t = (tid >= off) ? s[tid - off] : 0;
        __syncthreads();
        s[tid] += t;
        __syncthreads();
    }
    if (i < N_NODES) g_row_start[i] = s[tid] - v;   // exclusive within block
    if (tid == SCAN_B - 1) g_bsum[blockIdx.x] = s[tid];
}

__global__ __launch_bounds__(128) void scan2_kernel() {
    __shared__ int s[128];
    int tid = threadIdx.x;
    int v = (tid < N_SCAN_BLK) ? g_bsum[tid] : 0;
    s[tid] = v;
    __syncthreads();
#pragma unroll
    for (int off = 1; off < 128; off <<= 1) {
        int t = (tid >= off) ? s[tid - off] : 0;
        __syncthreads();
        s[tid] += t;
        __syncthreads();
    }
    if (tid < N_SCAN_BLK) g_boff[tid] = s[tid] - v; // exclusive block offsets
}

__global__ __launch_bounds__(SCAN_B) void scan3_kernel() {
    int i = blockIdx.x * SCAN_B + threadIdx.x;
    if (i < N_NODES) {
        int r = g_row_start[i] + g_boff[blockIdx.x];
        g_row_start[i] = r;
        g_cursor[i] = r;
    }
}

__global__ __launch_bounds__(256) void fill_kernel(const int* __restrict__ ei) {
    int e = blockIdx.x * blockDim.x + threadIdx.x;
    if (e >= N_EDGES) return;
    int s = ei[e];
    int d = ei[N_EDGES + e];
    int pos = atomicAdd(&g_cursor[d], 1);
    g_csr_src[pos] = s;
}

// ---------------------------------------------------------------------------
// GEMM1: hs1[i,:] = dinv[i] * (x[i,:] @ W1)   (M=100000, K=256, N=128)
// 128x128 tile, 256 threads, 8x8 microtile, BK=16.
__global__ __launch_bounds__(256) void gemm1_kernel(const float* __restrict__ x,
                                                    const float* __restrict__ W1) {
    __shared__ float As[16][132];   // transposed A chunk (+pad)
    __shared__ float Bs[16][132];
    const int tid  = threadIdx.x;
    const int tx   = tid & 15;       // 0..15 col group (8 cols each)
    const int ty   = tid >> 4;       // 0..15 row group (8 rows each)
    const int brow = blockIdx.x * 128;

    // A-load coords: 128 rows x 16 cols per chunk; 2 float4 per thread
    const int arow = tid >> 2;           // 0..63, +64 in pass 2
    const int ak   = (tid & 3) << 2;     // k offset 0,4,8,12
    // B-load coords: 16 rows x 128 cols per chunk; 2 float4 per thread
    const int bk   = tid >> 5;           // 0..7, +8 in pass 2
    const int bc   = (tid & 31) << 2;    // col 0..124

    float acc[8][8];
#pragma unroll
    for (int r = 0; r < 8; r++)
#pragma unroll
        for (int c = 0; c < 8; c++) acc[r][c] = 0.f;

    for (int kc = 0; kc < 256; kc += 16) {
#pragma unroll
        for (int p = 0; p < 2; p++) {
            int row = brow + arow + p * 64;
            float4 av = make_float4(0.f, 0.f, 0.f, 0.f);
            if (row < N_NODES) av = *(const float4*)(x + (size_t)row * 256 + kc + ak);
            As[ak + 0][arow + p * 64] = av.x;
            As[ak + 1][arow + p * 64] = av.y;
            As[ak + 2][arow + p * 64] = av.z;
            As[ak + 3][arow + p * 64] = av.w;
        }
#pragma unroll
        for (int p = 0; p < 2; p++) {
            int krow = bk + p * 8;
            float4 bv = *(const float4*)(W1 + (kc + krow) * 128 + bc);
            *(float4*)&Bs[krow][bc] = bv;
        }
        __syncthreads();
#pragma unroll
        for (int k = 0; k < 16; k++) {
            float4 a0 = *(const float4*)&As[k][ty << 3];
            float4 a1 = *(const float4*)&As[k][(ty << 3) + 4];
            float4 b0 = *(const float4*)&Bs[k][tx << 3];
            float4 b1 = *(const float4*)&Bs[k][(tx << 3) + 4];
            float a[8] = {a0.x, a0.y, a0.z, a0.w, a1.x, a1.y, a1.z, a1.w};
            float b[8] = {b0.x, b0.y, b0.z, b0.w, b1.x, b1.y, b1.z, b1.w};
#pragma unroll
            for (int r = 0; r < 8; r++)
#pragma unroll
                for (int c = 0; c < 8; c++)
                    acc[r][c] = fmaf(a[r], b[c], acc[r][c]);
        }
        __syncthreads();
    }
#pragma unroll
    for (int r = 0; r < 8; r++) {
        int row = brow + (ty << 3) + r;
        if (row < N_NODES) {
            float dv = g_dinv[row];
            float4 o0 = make_float4(acc[r][0] * dv, acc[r][1] * dv,
                                    acc[r][2] * dv, acc[r][3] * dv);
            float4 o1 = make_float4(acc[r][4] * dv, acc[r][5] * dv,
                                    acc[r][6] * dv, acc[r][7] * dv);
            *(float4*)&g_hs1[row * 128 + (tx << 3)]     = o0;
            *(float4*)&g_hs1[row * 128 + (tx << 3) + 4] = o1;
        }
    }
}

// ---------------------------------------------------------------------------
// Fused gather + finalize layer 1 + GEMM2: one warp per node.
// Lane-uniform index loads (L1-hit broadcast) + unroll-4 of independent
// LDG.128 row loads for MLP. acc = hs1[node] + sum_in hs1[s];
// h = relu(dinv*acc + b1);  hs2[node] = dinv * (h @ W2)
__global__ __launch_bounds__(256) void gather1_kernel(const float* __restrict__ b1,
                                                      const float* __restrict__ W2) {
    int node = (blockIdx.x * blockDim.x + threadIdx.x) >> 5;
    int lane = threadIdx.x & 31;
    if (node >= N_NODES) return;
    float dv = g_dinv[node];
    int beg = g_row_start[node];
    int end = beg + g_deg[node];
    const int fo = lane << 2;      // feature offset of this lane

    float4 acc = *(const float4*)&g_hs1[node * 128 + fo];   // self-loop

    int k = beg;
    for (; k + 3 < end; k += 4) {
        int s0 = g_csr_src[k];
        int s1 = g_csr_src[k + 1];
        int s2 = g_csr_src[k + 2];
        int s3 = g_csr_src[k + 3];
        float4 v0 = *(const float4*)&g_hs1[s0 * 128 + fo];
        float4 v1 = *(const float4*)&g_hs1[s1 * 128 + fo];
        float4 v2 = *(const float4*)&g_hs1[s2 * 128 + fo];
        float4 v3 = *(const float4*)&g_hs1[s3 * 128 + fo];
        acc.x += (v0.x + v1.x) + (v2.x + v3.x);
        acc.y += (v0.y + v1.y) + (v2.y + v3.y);
        acc.z += (v0.z + v1.z) + (v2.z + v3.z);
        acc.w += (v0.w + v1.w) + (v2.w + v3.w);
    }
    for (; k < end; k++) {
        int s0 = g_csr_src[k];
        float4 v0 = *(const float4*)&g_hs1[s0 * 128 + fo];
        acc.x += v0.x; acc.y += v0.y; acc.z += v0.z; acc.w += v0.w;
    }

    float4 bb = *(const float4*)&b1[fo];
    float hv[4];
    hv[0] = fmaxf(fmaf(dv, acc.x, bb.x), 0.f);
    hv[1] = fmaxf(fmaf(dv, acc.y, bb.y), 0.f);
    hv[2] = fmaxf(fmaf(dv, acc.z, bb.z), 0.f);
    hv[3] = fmaxf(fmaf(dv, acc.w, bb.w), 0.f);

    float p[8];
#pragma unroll
    for (int j = 0; j < 8; j++) p[j] = 0.f;
    const float* w2 = W2 + fo * 8;   // W2 row-major [128][8]
#pragma unroll
    for (int c = 0; c < 4; c++)
#pragma unroll
        for (int j = 0; j < 8; j++) p[j] = fmaf(hv[c], w2[c * 8 + j], p[j]);

#pragma unroll
    for (int offx = 16; offx > 0; offx >>= 1)
#pragma unroll
        for (int j = 0; j < 8; j++) p[j] += __shfl_xor_sync(0xffffffffu, p[j], offx);

    if (lane == 0) {
#pragma unroll
        for (int j = 0; j < 8; j++) g_hs2[node * 8 + j] = dv * p[j];
    }
}

// ---------------------------------------------------------------------------
// Fused gather + finalize layer 2: one warp per node, 4 edge slots x 8 feats.
__global__ __launch_bounds__(256) void gather2_kernel(const float* __restrict__ b2) {
    int node = (blockIdx.x * blockDim.x + threadIdx.x) >> 5;
    int lane = threadIdx.x & 31;
    if (node >= N_NODES) return;
    float dv = g_dinv[node];
    int beg = g_row_start[node];
    int end = beg + g_deg[node];
    int slot = lane >> 3;     // 0..3
    int j    = lane & 7;      // feature

    float acc = 0.f;
    for (int k = beg + slot; k < end; k += 4) {
        int s = g_csr_src[k];
        acc += g_hs2[s * 8 + j];
    }
    acc += __shfl_xor_sync(0xffffffffu, acc, 8);
    acc += __shfl_xor_sync(0xffffffffu, acc, 16);

    if (lane < 8) {
        float z = fmaf(dv, acc + g_hs2[node * 8 + lane], b2[lane]);
        g_z[node * 8 + lane] = z;
    }
}

// ---------------------------------------------------------------------------
// score[e] = sum_j z[a,j]*z[b,j] over concat(pos, neg)
__global__ __launch_bounds__(256) void score_kernel(const int* __restrict__ pos,
                                                    const int* __restrict__ neg,
                                                    float* __restrict__ out) {
    int e = blockIdx.x * blockDim.x + threadIdx.x;
    if (e >= 2 * N_PE) return;
    int ia, ib;
    if (e < N_PE) { ia = pos[e]; ib = pos[N_PE + e]; }
    else          { int t = e - N_PE; ia = neg[t]; ib = neg[N_PE + t]; }
    float4 za0 = *(const float4*)&g_z[ia * 8];
    float4 za1 = *(const float4*)&g_z[ia * 8 + 4];
    float4 zb0 = *(const float4*)&g_z[ib * 8];
    float4 zb1 = *(const float4*)&g_z[ib * 8 + 4];
    out[e] = za0.x * zb0.x + za0.y * zb0.y + za0.z * zb0.z + za0.w * zb0.w
           + za1.x * zb1.x + za1.y * zb1.y + za1.z * zb1.z + za1.w * zb1.w;
}

// ---------------------------------------------------------------------------
extern "C" void kernel_launch(void* const* d_in, const int* in_sizes, int n_in,
                              void* d_out, int out_size) {
    const float* x   = (const float*)d_in[0];
    const int*   ei  = (const int*)d_in[1];
    const int*   pos = (const int*)d_in[2];
    const int*   neg = (const int*)d_in[3];
    const float* W1  = (const float*)d_in[4];
    const float* b1  = (const float*)d_in[5];
    const float* W2  = (const float*)d_in[6];
    const float* b2  = (const float*)d_in[7];
    float* out = (float*)d_out;

    zero_deg_kernel<<<(N_NODES + 255) / 256, 256>>>();
    deg_kernel<<<N_EDGES / 256, 256>>>(ei + N_EDGES);
    dinv_kernel<<<(N_NODES + 255) / 256, 256>>>();
    scan1_kernel<<<N_SCAN_BLK, SCAN_B>>>();
    scan2_kernel<<<1, 128>>>();
    scan3_kernel<<<N_SCAN_BLK, SCAN_B>>>();
    fill_kernel<<<N_EDGES / 256, 256>>>(ei);
    gemm1_kernel<<<(N_NODES + 127) / 128, 256>>>(x, W1);
    gather1_kernel<<<(N_NODES * 32 + 255) / 256, 256>>>(b1, W2);
    gather2_kernel<<<(N_NODES * 32 + 255) / 256, 256>>>(b2);
    score_kernel<<<(2 * N_PE + 255) / 256, 256>>>(pos, neg, out);
}

// round 17
// speedup vs baseline: 1.1660x; 1.1660x over previous
#include <cuda_runtime.h>

#define N_NODES 100000
#define N_EDGES 1600000
#define N_PE    200000
#define F1 128
#define F2 8
#define SCAN_B 1024
#define N_SCAN_BLK ((N_NODES + SCAN_B - 1) / SCAN_B)   // 98

// Scratch (static device globals — no allocation allowed)
__device__ __align__(16) float g_hs1[N_NODES * F1];   // dinv-scaled x@W1
__device__ __align__(16) float g_hs2[N_NODES * F2];   // dinv-scaled h@W2
__device__ __align__(16) float g_z[N_NODES * F2];     // layer-2 output
__device__ __align__(16) float g_dinv[N_NODES];
__device__ __align__(16) int   g_deg[N_NODES];
__device__ __align__(16) int   g_row_start[N_NODES];  // exclusive prefix of deg
__device__ __align__(16) int   g_cursor[N_NODES];     // fill cursors
__device__ __align__(16) int   g_csr_src[N_EDGES];    // src grouped by dst
__device__ __align__(16) int   g_bsum[N_SCAN_BLK];
__device__ __align__(16) int   g_boff[N_SCAN_BLK];

// ---------------------------------------------------------------------------
__global__ __launch_bounds__(256) void zero_deg_kernel() {
    int i = blockIdx.x * blockDim.x + threadIdx.x;
    if (i < N_NODES) g_deg[i] = 0;
}

__global__ __launch_bounds__(256) void deg_kernel(const int* __restrict__ dst) {
    int e = blockIdx.x * blockDim.x + threadIdx.x;
    if (e < N_EDGES) atomicAdd(&g_deg[dst[e]], 1);
}

__global__ __launch_bounds__(256) void dinv_kernel() {
    int i = blockIdx.x * blockDim.x + threadIdx.x;
    if (i < N_NODES) g_dinv[i] = rsqrtf((float)g_deg[i] + 1.0f);
}

// --- prefix sum of g_deg -> g_row_start (exclusive), 3 phases ---------------
__global__ __launch_bounds__(SCAN_B) void scan1_kernel() {
    __shared__ int s[SCAN_B];
    int tid = threadIdx.x;
    int i = blockIdx.x * SCAN_B + tid;
    int v = (i < N_NODES) ? g_deg[i] : 0;
    s[tid] = v;
    __syncthreads();
#pragma unroll
    for (int off = 1; off < SCAN_B; off <<= 1) {
        int t = (tid >= off) ? s[tid - off] : 0;
        __syncthreads();
        s[tid] += t;
        __syncthreads();
    }
    if (i < N_NODES) g_row_start[i] = s[tid] - v;   // exclusive within block
    if (tid == SCAN_B - 1) g_bsum[blockIdx.x] = s[tid];
}

__global__ __launch_bounds__(128) void scan2_kernel() {
    __shared__ int s[128];
    int tid = threadIdx.x;
    int v = (tid < N_SCAN_BLK) ? g_bsum[tid] : 0;
    s[tid] = v;
    __syncthreads();
#pragma unroll
    for (int off = 1; off < 128; off <<= 1) {
        int t = (tid >= off) ? s[tid - off] : 0;
        __syncthreads();
        s[tid] += t;
        __syncthreads();
    }
    if (tid < N_SCAN_BLK) g_boff[tid] = s[tid] - v; // exclusive block offsets
}

__global__ __launch_bounds__(SCAN_B) void scan3_kernel() {
    int i = blockIdx.x * SCAN_B + threadIdx.x;
    if (i < N_NODES) {
        int r = g_row_start[i] + g_boff[blockIdx.x];
        g_row_start[i] = r;
        g_cursor[i] = r;
    }
}

__global__ __launch_bounds__(256) void fill_kernel(const int* __restrict__ ei) {
    int e = blockIdx.x * blockDim.x + threadIdx.x;
    if (e >= N_EDGES) return;
    int s = ei[e];
    int d = ei[N_EDGES + e];
    int pos = atomicAdd(&g_cursor[d], 1);
    g_csr_src[pos] = s;
}

// ---------------------------------------------------------------------------
__device__ __forceinline__ unsigned f2tf32(float f) {
    unsigned u;
    asm("cvt.rna.tf32.f32 %0, %1;" : "=r"(u) : "f"(f));
    return u;
}

// GEMM1 (tf32 tensor cores): hs1[i,:] = dinv[i] * (x[i,:] @ W1)
// M=100000, K=256, N=128. Block tile 128x128, 8 warps (4x2), warp tile 32x64.
// mma.m16n8k8: per warp 2 m-tiles x 8 n-tiles. tf32 conversion at staging.
__global__ __launch_bounds__(256) void gemm1_kernel(const float* __restrict__ x,
                                                    const float* __restrict__ W1) {
    __shared__ unsigned As[128][20];    // A chunk, tf32 bits, pad 20 (conflict-free frags)
    __shared__ unsigned Bs[128][17];    // B chunk transposed [n][k], pad 17
    const int tid    = threadIdx.x;
    const int lane   = tid & 31;
    const int wid    = tid >> 5;
    const int warp_m = wid & 3;         // 4 warps x 32 rows
    const int warp_n = wid >> 2;        // 2 warps x 64 cols
    const int brow   = blockIdx.x * 128;
    const int g      = lane >> 2;       // groupID 0..7
    const int t      = lane & 3;        // threadID_in_group 0..3

    // A staging coords: thread -> (row, 8-col half)
    const int s_row = tid >> 1;             // 0..127
    const int s_kof = (tid & 1) << 3;       // 0 or 8
    // B staging coords: thread -> (col n, 8-row half of k)
    const int s_n   = tid & 127;            // 0..127
    const int s_k8  = (tid >> 7) << 3;      // 0 or 8

    float acc[2][8][4];
#pragma unroll
    for (int mt = 0; mt < 2; mt++)
#pragma unroll
        for (int nt = 0; nt < 8; nt++)
#pragma unroll
            for (int i = 0; i < 4; i++) acc[mt][nt][i] = 0.f;

    for (int kc = 0; kc < 256; kc += 16) {
        // stage A (convert to tf32)
        {
            int grow = brow + s_row;
            float4 va = make_float4(0.f, 0.f, 0.f, 0.f);
            float4 vb = make_float4(0.f, 0.f, 0.f, 0.f);
            if (grow < N_NODES) {
                const float* p = x + (size_t)grow * 256 + kc + s_kof;
                va = *(const float4*)p;
                vb = *(const float4*)(p + 4);
            }
            uint4 ua = make_uint4(f2tf32(va.x), f2tf32(va.y), f2tf32(va.z), f2tf32(va.w));
            uint4 ub = make_uint4(f2tf32(vb.x), f2tf32(vb.y), f2tf32(vb.z), f2tf32(vb.w));
            *(uint4*)&As[s_row][s_kof]     = ua;
            *(uint4*)&As[s_row][s_kof + 4] = ub;
        }
        // stage B transposed (convert to tf32)
        {
#pragma unroll
            for (int i = 0; i < 8; i++) {
                float v = W1[(kc + s_k8 + i) * 128 + s_n];
                Bs[s_n][s_k8 + i] = f2tf32(v);
            }
        }
        __syncthreads();

#pragma unroll
        for (int ks = 0; ks < 16; ks += 8) {
            unsigned a[2][4];
#pragma unroll
            for (int mt = 0; mt < 2; mt++) {
                int rb = warp_m * 32 + mt * 16;
                a[mt][0] = As[rb + g][ks + t];
                a[mt][1] = As[rb + g + 8][ks + t];
                a[mt][2] = As[rb + g][ks + t + 4];
                a[mt][3] = As[rb + g + 8][ks + t + 4];
            }
            unsigned b[8][2];
#pragma unroll
            for (int nt = 0; nt < 8; nt++) {
                int cb = warp_n * 64 + nt * 8 + g;
                b[nt][0] = Bs[cb][ks + t];
                b[nt][1] = Bs[cb][ks + t + 4];
            }
#pragma unroll
            for (int mt = 0; mt < 2; mt++)
#pragma unroll
                for (int nt = 0; nt < 8; nt++) {
                    asm("mma.sync.aligned.m16n8k8.row.col.f32.tf32.tf32.f32 "
                        "{%0,%1,%2,%3}, {%4,%5,%6,%7}, {%8,%9}, {%0,%1,%2,%3};"
                        : "+f"(acc[mt][nt][0]), "+f"(acc[mt][nt][1]),
                          "+f"(acc[mt][nt][2]), "+f"(acc[mt][nt][3])
                        : "r"(a[mt][0]), "r"(a[mt][1]), "r"(a[mt][2]), "r"(a[mt][3]),
                          "r"(b[nt][0]), "r"(b[nt][1]));
                }
        }
        __syncthreads();
    }

    // epilogue: scale by dinv, write hs1
#pragma unroll
    for (int mt = 0; mt < 2; mt++) {
        int r0 = brow + warp_m * 32 + mt * 16 + g;
        int r1 = r0 + 8;
        float dv0 = (r0 < N_NODES) ? g_dinv[r0] : 0.f;
        float dv1 = (r1 < N_NODES) ? g_dinv[r1] : 0.f;
#pragma unroll
        for (int nt = 0; nt < 8; nt++) {
            int col = warp_n * 64 + nt * 8 + t * 2;
            if (r0 < N_NODES) {
                float2 o = make_float2(acc[mt][nt][0] * dv0, acc[mt][nt][1] * dv0);
                *(float2*)&g_hs1[r0 * 128 + col] = o;
            }
            if (r1 < N_NODES) {
                float2 o = make_float2(acc[mt][nt][2] * dv1, acc[mt][nt][3] * dv1);
                *(float2*)&g_hs1[r1 * 128 + col] = o;
            }
        }
    }
}

// ---------------------------------------------------------------------------
// Fused gather + finalize layer 1 + GEMM2: one warp per node.
// Lane-uniform index loads + unroll-4 of independent LDG.128 row loads.
// acc = hs1[node] + sum_in hs1[s]; h = relu(dinv*acc + b1);
// hs2[node] = dinv * (h @ W2)
__global__ __launch_bounds__(256) void gather1_kernel(const float* __restrict__ b1,
                                                      const float* __restrict__ W2) {
    int node = (blockIdx.x * blockDim.x + threadIdx.x) >> 5;
    int lane = threadIdx.x & 31;
    if (node >= N_NODES) return;
    float dv = g_dinv[node];
    int beg = g_row_start[node];
    int end = beg + g_deg[node];
    const int fo = lane << 2;      // feature offset of this lane

    float4 acc = *(const float4*)&g_hs1[node * 128 + fo];   // self-loop

    int k = beg;
    for (; k + 3 < end; k += 4) {
        int s0 = g_csr_src[k];
        int s1 = g_csr_src[k + 1];
        int s2 = g_csr_src[k + 2];
        int s3 = g_csr_src[k + 3];
        float4 v0 = *(const float4*)&g_hs1[s0 * 128 + fo];
        float4 v1 = *(const float4*)&g_hs1[s1 * 128 + fo];
        float4 v2 = *(const float4*)&g_hs1[s2 * 128 + fo];
        float4 v3 = *(const float4*)&g_hs1[s3 * 128 + fo];
        acc.x += (v0.x + v1.x) + (v2.x + v3.x);
        acc.y += (v0.y + v1.y) + (v2.y + v3.y);
        acc.z += (v0.z + v1.z) + (v2.z + v3.z);
        acc.w += (v0.w + v1.w) + (v2.w + v3.w);
    }
    for (; k < end; k++) {
        int s0 = g_csr_src[k];
        float4 v0 = *(const float4*)&g_hs1[s0 * 128 + fo];
        acc.x += v0.x; acc.y += v0.y; acc.z += v0.z; acc.w += v0.w;
    }

    float4 bb = *(const float4*)&b1[fo];
    float hv[4];
    hv[0] = fmaxf(fmaf(dv, acc.x, bb.x), 0.f);
    hv[1] = fmaxf(fmaf(dv, acc.y, bb.y), 0.f);
    hv[2] = fmaxf(fmaf(dv, acc.z, bb.z), 0.f);
    hv[3] = fmaxf(fmaf(dv, acc.w, bb.w), 0.f);

    float p[8];
#pragma unroll
    for (int j = 0; j < 8; j++) p[j] = 0.f;
    const float* w2 = W2 + fo * 8;   // W2 row-major [128][8]
#pragma unroll
    for (int c = 0; c < 4; c++)
#pragma unroll
        for (int j = 0; j < 8; j++) p[j] = fmaf(hv[c], w2[c * 8 + j], p[j]);

#pragma unroll
    for (int offx = 16; offx > 0; offx >>= 1)
#pragma unroll
        for (int j = 0; j < 8; j++) p[j] += __shfl_xor_sync(0xffffffffu, p[j], offx);

    if (lane == 0) {
#pragma unroll
        for (int j = 0; j < 8; j++) g_hs2[node * 8 + j] = dv * p[j];
    }
}

// ---------------------------------------------------------------------------
// Fused gather + finalize layer 2: one warp per node, 4 edge slots x 8 feats.
__global__ __launch_bounds__(256) void gather2_kernel(const float* __restrict__ b2) {
    int node = (blockIdx.x * blockDim.x + threadIdx.x) >> 5;
    int lane = threadIdx.x & 31;
    if (node >= N_NODES) return;
    float dv = g_dinv[node];
    int beg = g_row_start[node];
    int end = beg + g_deg[node];
    int slot = lane >> 3;     // 0..3
    int j    = lane & 7;      // feature

    float acc = 0.f;
    for (int k = beg + slot; k < end; k += 4) {
        int s = g_csr_src[k];
        acc += g_hs2[s * 8 + j];
    }
    acc += __shfl_xor_sync(0xffffffffu, acc, 8);
    acc += __shfl_xor_sync(0xffffffffu, acc, 16);

    if (lane < 8) {
        float z = fmaf(dv, acc + g_hs2[node * 8 + lane], b2[lane]);
        g_z[node * 8 + lane] = z;
    }
}

// ---------------------------------------------------------------------------
// score[e] = sum_j z[a,j]*z[b,j] over concat(pos, neg)
__global__ __launch_bounds__(256) void score_kernel(const int* __restrict__ pos,
                                                    const int* __restrict__ neg,
                                                    float* __restrict__ out) {
    int e = blockIdx.x * blockDim.x + threadIdx.x;
    if (e >= 2 * N_PE) return;
    int ia, ib;
    if (e < N_PE) { ia = pos[e]; ib = pos[N_PE + e]; }
    else          { int t = e - N_PE; ia = neg[t]; ib = neg[N_PE + t]; }
    float4 za0 = *(const float4*)&g_z[ia * 8];
    float4 za1 = *(const float4*)&g_z[ia * 8 + 4];
    float4 zb0 = *(const float4*)&g_z[ib * 8];
    float4 zb1 = *(const float4*)&g_z[ib * 8 + 4];
    out[e] = za0.x * zb0.x + za0.y * zb0.y + za0.z * zb0.z + za0.w * zb0.w
           + za1.x * zb1.x + za1.y * zb1.y + za1.z * zb1.z + za1.w * zb1.w;
}

// ---------------------------------------------------------------------------
extern "C" void kernel_launch(void* const* d_in, const int* in_sizes, int n_in,
                              void* d_out, int out_size) {
    const float* x   = (const float*)d_in[0];
    const int*   ei  = (const int*)d_in[1];
    const int*   pos = (const int*)d_in[2];
    const int*   neg = (const int*)d_in[3];
    const float* W1  = (const float*)d_in[4];
    const float* b1  = (const float*)d_in[5];
    const float* W2  = (const float*)d_in[6];
    const float* b2  = (const float*)d_in[7];
    float* out = (float*)d_out;

    zero_deg_kernel<<<(N_NODES + 255) / 256, 256>>>();
    deg_kernel<<<N_EDGES / 256, 256>>>(ei + N_EDGES);
    dinv_kernel<<<(N_NODES + 255) / 256, 256>>>();
    gemm1_kernel<<<(N_NODES + 127) / 128, 256>>>(x, W1);   // launch #4 -> profiled
    scan1_kernel<<<N_SCAN_BLK, SCAN_B>>>();
    scan2_kernel<<<1, 128>>>();
    scan3_kernel<<<N_SCAN_BLK, SCAN_B>>>();
    fill_kernel<<<N_EDGES / 256, 256>>>(ei);
    gather1_kernel<<<(N_NODES * 32 + 255) / 256, 256>>>(b1, W2);
    gather2_kernel<<<(N_NODES * 32 + 255) / 256, 256>>>(b2);
    score_kernel<<<(2 * N_PE + 255) / 256, 256>>>(pos, neg, out);
}